// round 9
// baseline (speedup 1.0000x reference)
#include <cuda_runtime.h>
#include <mma.h>
#include <cstdint>
#include <cstddef>

using namespace nvcuda;

#define N_TOK   8192
#define D_MODEL 4096
#define D_SAE   16384
#define K_SP    64
#define CAND_CAP 256

// ---------------- device scratch (no allocations allowed) ----------------
__device__ float g_wdecT[(size_t)D_SAE * D_MODEL];   // 256 MB: W_dec transposed (F, D)
__device__ int   g_tki[N_TOK * K_SP];
__device__ float g_tkv[N_TOK * K_SP];
__device__ int   g_cand[N_TOK * CAND_CAP];
__device__ int   g_ccnt[N_TOK];

// ---------------- helpers ----------------
__device__ __forceinline__ unsigned fkey(float f) {
    unsigned u = __float_as_uint(f);
    return u ^ ((u & 0x80000000u) ? 0xFFFFFFFFu : 0x80000000u);
}
__device__ __forceinline__ float fkey_inv(unsigned k) {
    unsigned u = (k & 0x80000000u) ? (k ^ 0x80000000u) : ~k;
    return __uint_as_float(u);
}

__device__ __forceinline__ void cp_async16(void* smem_dst, const void* gmem_src) {
    unsigned s = (unsigned)__cvta_generic_to_shared(smem_dst);
    asm volatile("cp.async.ca.shared.global [%0], [%1], 16;\n" :: "r"(s), "l"(gmem_src));
}
__device__ __forceinline__ void cp_commit() { asm volatile("cp.async.commit_group;\n"); }
template<int NN> __device__ __forceinline__ void cp_wait() {
    asm volatile("cp.async.wait_group %0;\n" :: "n"(NN));
}

// ================= W_dec transpose: (D_MODEL, D_SAE) -> (D_SAE, D_MODEL) =================
__global__ void __launch_bounds__(256)
transpose_kernel(const float* __restrict__ W) {
    __shared__ float t[32][33];
    int f0 = blockIdx.x * 32, d0 = blockIdx.y * 32;
    int tx = threadIdx.x, ty = threadIdx.y;   // (32, 8)
#pragma unroll
    for (int s = 0; s < 4; s++)
        t[ty + 8 * s][tx] = W[(size_t)(d0 + ty + 8 * s) * D_SAE + f0 + tx];
    __syncthreads();
#pragma unroll
    for (int s = 0; s < 4; s++)
        g_wdecT[(size_t)(f0 + ty + 8 * s) * D_MODEL + d0 + tx] = t[tx][ty + 8 * s];
}

// ================= encoder: pre = x @ W_enc^T + b_enc  (1xTF32 wmma, values only) =================
constexpr int BM = 128, BN = 64, BK = 32;
constexpr int LDA = BK + 4;                 // 36, skewed
constexpr int KT  = D_MODEL / BK;           // 128
constexpr int ENC_SMEM = (2 * BM * LDA + 2 * BN * LDA) * 4;   // 55296 B

__global__ void __launch_bounds__(256)
enc_kernel(const float* __restrict__ x, const float* __restrict__ W,
           const float* __restrict__ b, float* __restrict__ pre) {
    extern __shared__ float smem[];
    float* As0 = smem;
    float* As1 = As0 + BM * LDA;
    float* Bs0 = As1 + BM * LDA;
    float* Bs1 = Bs0 + BN * LDA;

    const int tid = threadIdx.x;
    const int m0 = blockIdx.y * BM;
    const int f0 = blockIdx.x * BN;

    const int lr = tid >> 3;            // 0..31
    const int lc = (tid & 7) << 2;      // 0,4,...,28

    const float* xg = x + (size_t)m0 * D_MODEL + lc;
    const float* wg = W + (size_t)f0 * D_MODEL + lc;

    const int wid = tid >> 5;
    const int wm = (wid >> 1) << 5;     // 0,32,64,96
    const int wn = (wid & 1) << 5;      // 0,32

    wmma::fragment<wmma::accumulator, 16, 16, 8, float> acc[2][2];
#pragma unroll
    for (int i = 0; i < 2; i++)
#pragma unroll
        for (int j = 0; j < 2; j++) wmma::fill_fragment(acc[i][j], 0.0f);

#pragma unroll
    for (int s = 0; s < 4; s++)
        cp_async16(As0 + (lr + 32 * s) * LDA + lc, xg + (size_t)(lr + 32 * s) * D_MODEL);
#pragma unroll
    for (int s = 0; s < 2; s++)
        cp_async16(Bs0 + (lr + 32 * s) * LDA + lc, wg + (size_t)(lr + 32 * s) * D_MODEL);
    cp_commit();

    for (int kt = 0; kt < KT; kt++) {
        float* Acur = (kt & 1) ? As1 : As0;
        float* Bcur = (kt & 1) ? Bs1 : Bs0;
        if (kt + 1 < KT) {
            float* An = (kt & 1) ? As0 : As1;
            float* Bn = (kt & 1) ? Bs0 : Bs1;
            const float* xg2 = xg + (size_t)(kt + 1) * BK;
            const float* wg2 = wg + (size_t)(kt + 1) * BK;
#pragma unroll
            for (int s = 0; s < 4; s++)
                cp_async16(An + (lr + 32 * s) * LDA + lc, xg2 + (size_t)(lr + 32 * s) * D_MODEL);
#pragma unroll
            for (int s = 0; s < 2; s++)
                cp_async16(Bn + (lr + 32 * s) * LDA + lc, wg2 + (size_t)(lr + 32 * s) * D_MODEL);
            cp_commit();
            cp_wait<1>();
        } else {
            cp_wait<0>();
        }
        __syncthreads();

#pragma unroll
        for (int kk = 0; kk < BK / 8; kk++) {
            wmma::fragment<wmma::matrix_a, 16, 16, 8, wmma::precision::tf32, wmma::row_major> a[2];
#pragma unroll
            for (int i = 0; i < 2; i++) {
                wmma::load_matrix_sync(a[i], Acur + (wm + 16 * i) * LDA + kk * 8, LDA);
#pragma unroll
                for (int t = 0; t < a[i].num_elements; t++)
                    a[i].x[t] = wmma::__float_to_tf32(a[i].x[t]);
            }
            wmma::fragment<wmma::matrix_b, 16, 16, 8, wmma::precision::tf32, wmma::col_major> bf[2];
#pragma unroll
            for (int j = 0; j < 2; j++) {
                wmma::load_matrix_sync(bf[j], Bcur + (wn + 16 * j) * LDA + kk * 8, LDA);
#pragma unroll
                for (int t = 0; t < bf[j].num_elements; t++)
                    bf[j].x[t] = wmma::__float_to_tf32(bf[j].x[t]);
            }
#pragma unroll
            for (int i = 0; i < 2; i++)
#pragma unroll
                for (int j = 0; j < 2; j++)
                    wmma::mma_sync(acc[i][j], a[i], bf[j], acc[i][j]);
        }
        __syncthreads();
    }

    // epilogue through shared (coalesced stores + bias)
    float* Cs = smem;   // 128 x 68
#pragma unroll
    for (int i = 0; i < 2; i++)
#pragma unroll
        for (int j = 0; j < 2; j++)
            wmma::store_matrix_sync(Cs + (wm + 16 * i) * 68 + (wn + 16 * j), acc[i][j], 68,
                                    wmma::mem_row_major);
    __syncthreads();

    const int rr = tid >> 4;           // 0..15
    const int cc = (tid & 15) << 2;    // 0..60
    float4 bb = *(const float4*)(b + f0 + cc);
#pragma unroll
    for (int s = 0; s < 8; s++) {
        int r = rr + 16 * s;
        float4 v;
        v.x = Cs[r * 68 + cc + 0] + bb.x;
        v.y = Cs[r * 68 + cc + 1] + bb.y;
        v.z = Cs[r * 68 + cc + 2] + bb.z;
        v.w = Cs[r * 68 + cc + 3] + bb.w;
        *(float4*)(pre + (size_t)(m0 + r) * D_SAE + f0 + cc) = v;
    }
}

// ================= candidate collection: radix-select T64, keep val >= T64 - MARGIN =================
constexpr int TOPK_SMEM = D_SAE * 4;   // 64 KB row cache
#define SEL_MARGIN 1.2e-3f

__global__ void __launch_bounds__(256)
topk_kernel(const float* __restrict__ pre) {
    extern __shared__ float sh[];
    __shared__ unsigned hist[256];
    __shared__ int s_digit, s_above, s_slot;

    const int n = blockIdx.x;
    const int tid = threadIdx.x;
    const float4* rowv = (const float4*)(pre + (size_t)n * D_SAE);
    float4* shv = (float4*)sh;

    for (int i = tid; i < D_SAE / 4; i += 256) shv[i] = rowv[i];
    __syncthreads();

    unsigned prefix = 0, mask = 0;
    int need = K_SP;
#pragma unroll
    for (int pass = 0; pass < 4; pass++) {
        int shift = 24 - 8 * pass;
        hist[tid] = 0;
        __syncthreads();
        for (int i = tid; i < D_SAE; i += 256) {
            unsigned k = fkey(sh[i]);
            if ((k & mask) == prefix) atomicAdd(&hist[(k >> shift) & 255u], 1u);
        }
        __syncthreads();
        if (tid == 0) {
            int c = 0, d = 255;
            for (; d >= 0; d--) {
                int h = (int)hist[d];
                if (c + h >= need) break;
                c += h;
            }
            s_digit = d;
            s_above = c;
        }
        __syncthreads();
        prefix |= ((unsigned)s_digit) << shift;
        mask   |= (0xFFu << shift);
        need   -= s_above;
        __syncthreads();
    }
    const float thresh = fkey_inv(prefix) - SEL_MARGIN;   // T64 value minus safety margin

    if (tid == 0) s_slot = 0;
    __syncthreads();

    for (int i = tid; i < D_SAE; i += 256) {
        if (sh[i] >= thresh) {
            int slot = atomicAdd(&s_slot, 1);
            if (slot < CAND_CAP) g_cand[n * CAND_CAP + slot] = i;
        }
    }
    __syncthreads();
    if (tid == 0) g_ccnt[n] = (s_slot < CAND_CAP) ? s_slot : CAND_CAP;
}

// ================= fp64 rescore + exact top-64 + write sparse row =================
__global__ void __launch_bounds__(256)
rescore_kernel(const float* __restrict__ x, const float* __restrict__ W,
               const float* __restrict__ pre, float* __restrict__ sparse) {
    __shared__ int    s_idx[CAND_CAP];
    __shared__ double s_val[CAND_CAP];

    const int n = blockIdx.x;
    const int tid = threadIdx.x;
    const int wid = tid >> 5;
    const int lane = tid & 31;

    const int c = g_ccnt[n];
    for (int i = tid; i < c; i += 256) s_idx[i] = g_cand[n * CAND_CAP + i];
    __syncthreads();

    const float* xr = x + (size_t)n * D_MODEL;

    // warp per candidate, 4 independent fp64 chains per lane to hide DFMA latency
    for (int ci = wid; ci < c; ci += 8) {
        const float* wr = W + (size_t)s_idx[ci] * D_MODEL;
        double a0 = 0.0, a1 = 0.0, a2 = 0.0, a3 = 0.0;
        for (int kb = 0; kb < D_MODEL; kb += 128) {
            a0 = fma((double)xr[kb + lane],      (double)wr[kb + lane],      a0);
            a1 = fma((double)xr[kb + 32 + lane], (double)wr[kb + 32 + lane], a1);
            a2 = fma((double)xr[kb + 64 + lane], (double)wr[kb + 64 + lane], a2);
            a3 = fma((double)xr[kb + 96 + lane], (double)wr[kb + 96 + lane], a3);
        }
        double s = (a0 + a1) + (a2 + a3);
#pragma unroll
        for (int o = 16; o > 0; o >>= 1) s += __shfl_down_sync(0xFFFFFFFFu, s, o);
        if (lane == 0) s_val[ci] = s;
    }
    __syncthreads();

    // zero the sparse output row
    float4* srow = (float4*)(sparse + (size_t)n * D_SAE);
    float4 z = make_float4(0.f, 0.f, 0.f, 0.f);
    for (int i = tid; i < D_SAE / 4; i += 256) srow[i] = z;
    __syncthreads();

    // exact ranking among candidates (desc value, asc feature index on ties)
    if (tid < c) {
        double v = s_val[tid];
        int my = s_idx[tid];
        int rank = 0;
        for (int j = 0; j < c; j++)
            rank += (s_val[j] > v) || (s_val[j] == v && s_idx[j] < my);
        if (rank < K_SP) {
            float pv = pre[(size_t)n * D_SAE + my];   // reference-like fp32 value
            sparse[(size_t)n * D_SAE + my] = pv;
            g_tki[n * K_SP + rank] = my;
            g_tkv[n * K_SP + rank] = pv;
        }
    }
}

// ================= sparse decoder: recon = sum_j v_j * W_decT[f_j,:] + b_dec =================
__global__ void __launch_bounds__(256)
dec_kernel(const float* __restrict__ bdec, float* __restrict__ recon) {
    __shared__ float sv[K_SP];
    __shared__ int   si[K_SP];
    const int n = blockIdx.x;
    const int tid = threadIdx.x;
    if (tid < K_SP) { si[tid] = g_tki[n * K_SP + tid]; sv[tid] = g_tkv[n * K_SP + tid]; }
    __syncthreads();

    float4 accv[4];
    const float4* bv = (const float4*)bdec;
#pragma unroll
    for (int i = 0; i < 4; i++) accv[i] = bv[tid + 256 * i];

#pragma unroll 2
    for (int j = 0; j < K_SP; j++) {
        const float4* wr = (const float4*)(g_wdecT + (size_t)si[j] * D_MODEL);
        float v = sv[j];
#pragma unroll
        for (int i = 0; i < 4; i++) {
            float4 w = wr[tid + 256 * i];
            accv[i].x = fmaf(v, w.x, accv[i].x);
            accv[i].y = fmaf(v, w.y, accv[i].y);
            accv[i].z = fmaf(v, w.z, accv[i].z);
            accv[i].w = fmaf(v, w.w, accv[i].w);
        }
    }
    float4* out = (float4*)(recon + (size_t)n * D_MODEL);
#pragma unroll
    for (int i = 0; i < 4; i++) out[tid + 256 * i] = accv[i];
}

// ================= launch =================
extern "C" void kernel_launch(void* const* d_in, const int* in_sizes, int n_in,
                              void* d_out, int out_size) {
    const float* x     = (const float*)d_in[0];
    const float* W_enc = (const float*)d_in[1];
    const float* b_enc = (const float*)d_in[2];
    const float* W_dec = (const float*)d_in[3];
    const float* b_dec = (const float*)d_in[4];

    float* recon  = (float*)d_out;                              // (N, D)
    float* sparse = recon + (size_t)N_TOK * D_MODEL;            // (N, F)
    float* pre    = sparse + (size_t)N_TOK * D_SAE;             // (N, F)

    cudaFuncSetAttribute(enc_kernel,  cudaFuncAttributeMaxDynamicSharedMemorySize, ENC_SMEM);
    cudaFuncSetAttribute(topk_kernel, cudaFuncAttributeMaxDynamicSharedMemorySize, TOPK_SMEM);

    transpose_kernel<<<dim3(D_SAE / 32, D_MODEL / 32), dim3(32, 8)>>>(W_dec);
    enc_kernel<<<dim3(D_SAE / BN, N_TOK / BM), 256, ENC_SMEM>>>(x, W_enc, b_enc, pre);
    topk_kernel<<<N_TOK, 256, TOPK_SMEM>>>(pre);
    rescore_kernel<<<N_TOK, 256>>>(x, W_enc, pre, sparse);
    dec_kernel<<<N_TOK, 256>>>(b_dec, recon);
}

// round 13
// speedup vs baseline: 1.2278x; 1.2278x over previous
#include <cuda_runtime.h>
#include <cstdint>
#include <cstddef>

#define N_TOK   8192
#define D_MODEL 4096
#define D_SAE   16384
#define K_SP    64
#define CAND_CAP 256

// ---------------- device scratch (no allocations allowed) ----------------
__device__ float g_wdecT[(size_t)D_SAE * D_MODEL];   // 256 MB: W_dec transposed (F, D)
__device__ int   g_tki[N_TOK * K_SP];
__device__ float g_tkv[N_TOK * K_SP];
__device__ int   g_cand[N_TOK * CAND_CAP];
__device__ int   g_ccnt[N_TOK];

// ---------------- helpers ----------------
__device__ __forceinline__ unsigned fkey(float f) {
    unsigned u = __float_as_uint(f);
    return u ^ ((u & 0x80000000u) ? 0xFFFFFFFFu : 0x80000000u);
}
__device__ __forceinline__ float fkey_inv(unsigned k) {
    unsigned u = (k & 0x80000000u) ? (k ^ 0x80000000u) : ~k;
    return __uint_as_float(u);
}
__device__ __forceinline__ float to_tf32(float x) {
    float r;
    asm("cvt.rn.tf32.f32 %0, %1;" : "=f"(r) : "f"(x));
    return r;
}
__device__ __forceinline__ void mma_tf32(float* c, const uint32_t* a, const uint32_t* b) {
    asm volatile(
        "mma.sync.aligned.m16n8k8.row.col.f32.tf32.tf32.f32 "
        "{%0,%1,%2,%3}, {%4,%5,%6,%7}, {%8,%9}, {%0,%1,%2,%3};"
        : "+f"(c[0]), "+f"(c[1]), "+f"(c[2]), "+f"(c[3])
        : "r"(a[0]), "r"(a[1]), "r"(a[2]), "r"(a[3]), "r"(b[0]), "r"(b[1]));
}

// ================= W_dec transpose: (D_MODEL, D_SAE) -> (D_SAE, D_MODEL) =================
__global__ void __launch_bounds__(256)
transpose_kernel(const float* __restrict__ W) {
    __shared__ float t[32][33];
    int f0 = blockIdx.x * 32, d0 = blockIdx.y * 32;
    int tx = threadIdx.x, ty = threadIdx.y;   // (32, 8)
#pragma unroll
    for (int s = 0; s < 4; s++)
        t[ty + 8 * s][tx] = W[(size_t)(d0 + ty + 8 * s) * D_SAE + f0 + tx];
    __syncthreads();
#pragma unroll
    for (int s = 0; s < 4; s++)
        g_wdecT[(size_t)(f0 + ty + 8 * s) * D_MODEL + d0 + tx] = t[tx][ty + 8 * s];
}

// ================= encoder: pre = x @ W_enc^T + b_enc  (mma.sync m16n8k8 tf32) =================
// CTA tile 128x128, BK=16, 8 warps of 32x64. smem rows hold 16 k-floats with the
// permutation slot(k) = (k&3)*2 + ((k&7)>>2) + (k>=8)*8 so that fragment pairs
// (k, k+4) are adjacent -> every A/B fragment piece is a single LDS.64.
constexpr int BM = 128, BN = 128, BK = 16;
constexpr int SLD = 18;                      // padded row stride (floats)
constexpr int EKT = D_MODEL / BK;            // 256

__global__ void __launch_bounds__(256, 2)
enc_mma_kernel(const float* __restrict__ x, const float* __restrict__ W,
               const float* __restrict__ b, float* __restrict__ pre) {
    __shared__ float As[2][BM * SLD];
    __shared__ float Bs[2][BN * SLD];

    const int tid = threadIdx.x;
    const int bid = blockIdx.x;
    // 256-CTA chunks of 16m x 16n tiles for L2 reuse (wave ~ 296 CTAs)
    const int chunk = bid >> 8, lid = bid & 255;
    const int m0 = ((chunk & 3) * 16 + (lid & 15)) * BM;
    const int f0 = ((chunk >> 2) * 16 + (lid >> 4)) * BN;

    const int lane = tid & 31, wid = tid >> 5;
    const int g = lane >> 2, t = lane & 3;
    const int wm = (wid & 3) * 32, wn = (wid >> 2) * 64;

    // producer: thread handles rows r0 and r0+64 (same q) for both A and B
    const int r0 = tid >> 2, q = tid & 3;
    const int sb = (q >> 1) * 8 + (q & 1);      // slot base for k = 4q..4q+3
    const float* xg = x + (size_t)(m0 + r0) * D_MODEL + q * 4;
    const float* wg = W + (size_t)(f0 + r0) * D_MODEL + q * 4;
    const size_t R64 = (size_t)64 * D_MODEL;

    float acc[2][8][4];
#pragma unroll
    for (int i = 0; i < 2; i++)
#pragma unroll
        for (int j = 0; j < 8; j++)
#pragma unroll
            for (int u = 0; u < 4; u++) acc[i][j][u] = 0.0f;

    float4 ax0 = *(const float4*)(xg);
    float4 ax1 = *(const float4*)(xg + R64);
    float4 bx0 = *(const float4*)(wg);
    float4 bx1 = *(const float4*)(wg + R64);

#define STORE_STAGE(s)                                                          \
    do {                                                                        \
        float* A_ = As[s]; float* B_ = Bs[s];                                   \
        float av0[4] = { ax0.x, ax0.y, ax0.z, ax0.w };                          \
        float av1[4] = { ax1.x, ax1.y, ax1.z, ax1.w };                          \
        float bv0[4] = { bx0.x, bx0.y, bx0.z, bx0.w };                          \
        float bv1[4] = { bx1.x, bx1.y, bx1.z, bx1.w };                          \
        _Pragma("unroll")                                                       \
        for (int j = 0; j < 4; j++) {                                           \
            A_[r0 * SLD + sb + 2 * j]        = to_tf32(av0[j]);                 \
            A_[(r0 + 64) * SLD + sb + 2 * j] = to_tf32(av1[j]);                 \
            B_[r0 * SLD + sb + 2 * j]        = to_tf32(bv0[j]);                 \
            B_[(r0 + 64) * SLD + sb + 2 * j] = to_tf32(bv1[j]);                 \
        }                                                                       \
    } while (0)

    STORE_STAGE(0);
    __syncthreads();

    for (int kt = 0; kt < EKT; kt++) {
        const int cur = kt & 1;
        if (kt + 1 < EKT) {
            const float* xp = xg + (size_t)(kt + 1) * BK;
            const float* wp = wg + (size_t)(kt + 1) * BK;
            ax0 = *(const float4*)(xp);
            ax1 = *(const float4*)(xp + R64);
            bx0 = *(const float4*)(wp);
            bx1 = *(const float4*)(wp + R64);
        }

        const float* A_ = As[cur];
        const float* B_ = Bs[cur];
#pragma unroll
        for (int ks = 0; ks < 2; ks++) {
            const int ko = ks * 8 + 2 * t;
            uint32_t af[2][4];
#pragma unroll
            for (int mt = 0; mt < 2; mt++) {
                float2 lo = *(const float2*)&A_[(wm + mt * 16 + g) * SLD + ko];
                float2 hi = *(const float2*)&A_[(wm + mt * 16 + g + 8) * SLD + ko];
                af[mt][0] = __float_as_uint(lo.x);
                af[mt][1] = __float_as_uint(hi.x);
                af[mt][2] = __float_as_uint(lo.y);
                af[mt][3] = __float_as_uint(hi.y);
            }
#pragma unroll
            for (int nt = 0; nt < 8; nt++) {
                float2 bv = *(const float2*)&B_[(wn + nt * 8 + g) * SLD + ko];
                uint32_t bf[2] = { __float_as_uint(bv.x), __float_as_uint(bv.y) };
                mma_tf32(acc[0][nt], af[0], bf);
                mma_tf32(acc[1][nt], af[1], bf);
            }
        }

        if (kt + 1 < EKT) STORE_STAGE((kt + 1) & 1);
        __syncthreads();
    }
#undef STORE_STAGE

    // epilogue: add bias, store (c0,c1)->(row g), (c2,c3)->(row g+8)
#pragma unroll
    for (int nt = 0; nt < 8; nt++) {
        const int col = f0 + wn + nt * 8 + 2 * t;
        float2 bb = *(const float2*)(b + col);
#pragma unroll
        for (int mt = 0; mt < 2; mt++) {
            const int row = m0 + wm + mt * 16 + g;
            float2 v0 = make_float2(acc[mt][nt][0] + bb.x, acc[mt][nt][1] + bb.y);
            float2 v1 = make_float2(acc[mt][nt][2] + bb.x, acc[mt][nt][3] + bb.y);
            *(float2*)(pre + (size_t)row * D_SAE + col) = v0;
            *(float2*)(pre + (size_t)(row + 8) * D_SAE + col) = v1;
        }
    }
}

// ================= candidate collection: radix-select T64, keep val >= T64 - MARGIN =================
constexpr int TOPK_SMEM = D_SAE * 4;   // 64 KB row cache
#define SEL_MARGIN 1.2e-3f

__global__ void __launch_bounds__(256)
topk_kernel(const float* __restrict__ pre) {
    extern __shared__ float sh[];
    __shared__ unsigned hist[256];
    __shared__ int s_digit, s_above, s_slot;

    const int n = blockIdx.x;
    const int tid = threadIdx.x;
    const float4* rowv = (const float4*)(pre + (size_t)n * D_SAE);
    float4* shv = (float4*)sh;

    for (int i = tid; i < D_SAE / 4; i += 256) shv[i] = rowv[i];
    __syncthreads();

    unsigned prefix = 0, mask = 0;
    int need = K_SP;
#pragma unroll
    for (int pass = 0; pass < 4; pass++) {
        int shift = 24 - 8 * pass;
        hist[tid] = 0;
        __syncthreads();
        for (int i = tid; i < D_SAE; i += 256) {
            unsigned k = fkey(sh[i]);
            if ((k & mask) == prefix) atomicAdd(&hist[(k >> shift) & 255u], 1u);
        }
        __syncthreads();
        if (tid == 0) {
            int cc = 0, d = 255;
            for (; d >= 0; d--) {
                int h = (int)hist[d];
                if (cc + h >= need) break;
                cc += h;
            }
            s_digit = d;
            s_above = cc;
        }
        __syncthreads();
        prefix |= ((unsigned)s_digit) << shift;
        mask   |= (0xFFu << shift);
        need   -= s_above;
        __syncthreads();
    }
    const float thresh = fkey_inv(prefix) - SEL_MARGIN;

    if (tid == 0) s_slot = 0;
    __syncthreads();

    for (int i = tid; i < D_SAE; i += 256) {
        if (sh[i] >= thresh) {
            int slot = atomicAdd(&s_slot, 1);
            if (slot < CAND_CAP) g_cand[n * CAND_CAP + slot] = i;
        }
    }
    __syncthreads();
    if (tid == 0) g_ccnt[n] = (s_slot < CAND_CAP) ? s_slot : CAND_CAP;
}

// ================= fp64 rescore + exact top-64 + write sparse row =================
__global__ void __launch_bounds__(256)
rescore_kernel(const float* __restrict__ x, const float* __restrict__ W,
               const float* __restrict__ pre, float* __restrict__ sparse) {
    __shared__ int    s_idx[CAND_CAP];
    __shared__ double s_val[CAND_CAP];

    const int n = blockIdx.x;
    const int tid = threadIdx.x;
    const int wid = tid >> 5;
    const int lane = tid & 31;

    const int c = g_ccnt[n];
    for (int i = tid; i < c; i += 256) s_idx[i] = g_cand[n * CAND_CAP + i];
    __syncthreads();

    const float* xr = x + (size_t)n * D_MODEL;

    for (int ci = wid; ci < c; ci += 8) {
        const float* wr = W + (size_t)s_idx[ci] * D_MODEL;
        double a0 = 0.0, a1 = 0.0, a2 = 0.0, a3 = 0.0;
        for (int kb = 0; kb < D_MODEL; kb += 128) {
            a0 = fma((double)xr[kb + lane],      (double)wr[kb + lane],      a0);
            a1 = fma((double)xr[kb + 32 + lane], (double)wr[kb + 32 + lane], a1);
            a2 = fma((double)xr[kb + 64 + lane], (double)wr[kb + 64 + lane], a2);
            a3 = fma((double)xr[kb + 96 + lane], (double)wr[kb + 96 + lane], a3);
        }
        double s = (a0 + a1) + (a2 + a3);
#pragma unroll
        for (int o = 16; o > 0; o >>= 1) s += __shfl_down_sync(0xFFFFFFFFu, s, o);
        if (lane == 0) s_val[ci] = s;
    }
    __syncthreads();

    float4* srow = (float4*)(sparse + (size_t)n * D_SAE);
    float4 z = make_float4(0.f, 0.f, 0.f, 0.f);
    for (int i = tid; i < D_SAE / 4; i += 256) srow[i] = z;
    __syncthreads();

    if (tid < c) {
        double v = s_val[tid];
        int my = s_idx[tid];
        int rank = 0;
        for (int j = 0; j < c; j++)
            rank += (s_val[j] > v) || (s_val[j] == v && s_idx[j] < my);
        if (rank < K_SP) {
            float pv = pre[(size_t)n * D_SAE + my];
            sparse[(size_t)n * D_SAE + my] = pv;
            g_tki[n * K_SP + rank] = my;
            g_tkv[n * K_SP + rank] = pv;
        }
    }
}

// ================= sparse decoder: recon = sum_j v_j * W_decT[f_j,:] + b_dec =================
__global__ void __launch_bounds__(256)
dec_kernel(const float* __restrict__ bdec, float* __restrict__ recon) {
    __shared__ float sv[K_SP];
    __shared__ int   si[K_SP];
    const int n = blockIdx.x;
    const int tid = threadIdx.x;
    if (tid < K_SP) { si[tid] = g_tki[n * K_SP + tid]; sv[tid] = g_tkv[n * K_SP + tid]; }
    __syncthreads();

    float4 accv[4];
    const float4* bv = (const float4*)bdec;
#pragma unroll
    for (int i = 0; i < 4; i++) accv[i] = bv[tid + 256 * i];

#pragma unroll 2
    for (int j = 0; j < K_SP; j++) {
        const float4* wr = (const float4*)(g_wdecT + (size_t)si[j] * D_MODEL);
        float v = sv[j];
#pragma unroll
        for (int i = 0; i < 4; i++) {
            float4 w = wr[tid + 256 * i];
            accv[i].x = fmaf(v, w.x, accv[i].x);
            accv[i].y = fmaf(v, w.y, accv[i].y);
            accv[i].z = fmaf(v, w.z, accv[i].z);
            accv[i].w = fmaf(v, w.w, accv[i].w);
        }
    }
    float4* out = (float4*)(recon + (size_t)n * D_MODEL);
#pragma unroll
    for (int i = 0; i < 4; i++) out[tid + 256 * i] = accv[i];
}

// ================= launch =================
extern "C" void kernel_launch(void* const* d_in, const int* in_sizes, int n_in,
                              void* d_out, int out_size) {
    const float* x     = (const float*)d_in[0];
    const float* W_enc = (const float*)d_in[1];
    const float* b_enc = (const float*)d_in[2];
    const float* W_dec = (const float*)d_in[3];
    const float* b_dec = (const float*)d_in[4];

    float* recon  = (float*)d_out;                              // (N, D)
    float* sparse = recon + (size_t)N_TOK * D_MODEL;            // (N, F)
    float* pre    = sparse + (size_t)N_TOK * D_SAE;             // (N, F)

    cudaFuncSetAttribute(topk_kernel, cudaFuncAttributeMaxDynamicSharedMemorySize, TOPK_SMEM);

    transpose_kernel<<<dim3(D_SAE / 32, D_MODEL / 32), dim3(32, 8)>>>(W_dec);
    enc_mma_kernel<<<(N_TOK / BM) * (D_SAE / BN), 256>>>(x, W_enc, b_enc, pre);
    topk_kernel<<<N_TOK, 256, TOPK_SMEM>>>(pre);
    rescore_kernel<<<N_TOK, 256>>>(x, W_enc, pre, sparse);
    dec_kernel<<<N_TOK, 256>>>(b_dec, recon);
}

// round 14
// speedup vs baseline: 1.4517x; 1.1824x over previous
#include <cuda_runtime.h>
#include <cuda_fp16.h>
#include <cstdint>
#include <cstddef>

#define N_TOK   8192
#define D_MODEL 4096
#define D_SAE   16384
#define K_SP    64
#define CAND_CAP 256

// ---------------- device scratch (no allocations allowed) ----------------
__device__ float g_wdecT[(size_t)D_SAE * D_MODEL];   // 256 MB: W_dec transposed (F, D)
__device__ int   g_tki[N_TOK * K_SP];
__device__ float g_tkv[N_TOK * K_SP];
__device__ int   g_cand[N_TOK * CAND_CAP];
__device__ int   g_ccnt[N_TOK];

// ---------------- helpers ----------------
__device__ __forceinline__ unsigned fkey(float f) {
    unsigned u = __float_as_uint(f);
    return u ^ ((u & 0x80000000u) ? 0xFFFFFFFFu : 0x80000000u);
}
__device__ __forceinline__ float fkey_inv(unsigned k) {
    unsigned u = (k & 0x80000000u) ? (k ^ 0x80000000u) : ~k;
    return __uint_as_float(u);
}
__device__ __forceinline__ uint32_t f2h2(float lo, float hi) {
    // cvt.rn.f16x2.f32 d, a, b  packs a into the UPPER half, b into the LOWER half
    uint32_t r;
    asm("cvt.rn.f16x2.f32 %0, %1, %2;" : "=r"(r) : "f"(hi), "f"(lo));
    return r;
}
__device__ __forceinline__ uint32_t smem_u32(const void* p) {
    uint32_t a;
    asm("{ .reg .u64 t; cvta.to.shared.u64 t, %1; cvt.u32.u64 %0, t; }" : "=r"(a) : "l"(p));
    return a;
}
__device__ __forceinline__ void ldsm4(uint32_t* r, uint32_t addr) {
    asm volatile("ldmatrix.sync.aligned.m8n8.x4.shared.b16 {%0,%1,%2,%3}, [%4];"
        : "=r"(r[0]), "=r"(r[1]), "=r"(r[2]), "=r"(r[3]) : "r"(addr));
}
__device__ __forceinline__ void mma_h(float* c, const uint32_t* a, const uint32_t* b) {
    asm volatile(
        "mma.sync.aligned.m16n8k16.row.col.f32.f16.f16.f32 "
        "{%0,%1,%2,%3}, {%4,%5,%6,%7}, {%8,%9}, {%0,%1,%2,%3};"
        : "+f"(c[0]), "+f"(c[1]), "+f"(c[2]), "+f"(c[3])
        : "r"(a[0]), "r"(a[1]), "r"(a[2]), "r"(a[3]), "r"(b[0]), "r"(b[1]));
}

// no-op kernels to shift the ncu -s window onto the encoder launch
__global__ void noop_kernel() {}

// ================= W_dec transpose: (D_MODEL, D_SAE) -> (D_SAE, D_MODEL) =================
__global__ void __launch_bounds__(256)
transpose_kernel(const float* __restrict__ W) {
    __shared__ float t[32][33];
    int f0 = blockIdx.x * 32, d0 = blockIdx.y * 32;
    int tx = threadIdx.x, ty = threadIdx.y;   // (32, 8)
#pragma unroll
    for (int s = 0; s < 4; s++)
        t[ty + 8 * s][tx] = W[(size_t)(d0 + ty + 8 * s) * D_SAE + f0 + tx];
    __syncthreads();
#pragma unroll
    for (int s = 0; s < 4; s++)
        g_wdecT[(size_t)(f0 + ty + 8 * s) * D_MODEL + d0 + tx] = t[tx][ty + 8 * s];
}

// ================= encoder: pre = x @ W_enc^T + b_enc  (mma.sync m16n8k16 fp16) =================
// CTA tile 128x128, BK=32, 512 threads = 16 warps of 32x32.
// smem tiles fp16 [128][40] (80-byte rows: banks 20r mod 32 -> conflict-free LDSM).
// fp16 values feed the MMA; top-64 selection is protected by the fp64 rescore.
constexpr int HBM = 128, HBN = 128, HBK = 32;
constexpr int HLD = 40;                       // fp16 elems per row (80 B)
constexpr int HKT = D_MODEL / HBK;            // 128
constexpr int STAGE_H = HBM * HLD;            // halfs per stage

__global__ void __launch_bounds__(512, 1)
enc_h_kernel(const float* __restrict__ x, const float* __restrict__ W,
             const float* __restrict__ b, float* __restrict__ pre) {
    __shared__ __half As[2][STAGE_H];
    __shared__ __half Bs[2][STAGE_H];

    const int tid = threadIdx.x;
    const int bid = blockIdx.x;
    // 256-CTA chunks of 16m x 16n tiles for L2 reuse
    const int chunk = bid >> 8, lid = bid & 255;
    const int m0 = ((chunk & 3) * 16 + (lid & 15)) * HBM;
    const int f0 = ((chunk >> 2) * 16 + (lid >> 4)) * HBN;

    const int lane = tid & 31, wid = tid >> 5;          // 16 warps
    const int g = lane >> 2, t = lane & 3;
    const int wm = (wid & 3) * 32, wn = (wid >> 2) * 32;

    // producer: thread handles 8 floats of one row for A and for B
    const int pr = tid >> 2, pq = tid & 3;              // row 0..127, col-block 0..3
    const float* xg = x + (size_t)(m0 + pr) * D_MODEL + pq * 8;
    const float* wg = W + (size_t)(f0 + pr) * D_MODEL + pq * 8;
    __half* Adst = &As[0][pr * HLD + pq * 8];
    __half* Bdst = &Bs[0][pr * HLD + pq * 8];

    // ldmatrix source offsets (bytes), stage-relative
    const uint32_t a_base = smem_u32(&As[0][0]);
    const uint32_t b_base = smem_u32(&Bs[0][0]);
    const uint32_t a_off = ((wm + (lane & 15)) * HLD + ((lane >> 4) << 3)) * 2;
    const uint32_t b_off = ((wn + (lane & 7) + ((lane >> 4) << 3)) * HLD
                            + (((lane >> 3) & 1) << 3)) * 2;

    float acc[2][4][4];
#pragma unroll
    for (int i = 0; i < 2; i++)
#pragma unroll
        for (int j = 0; j < 4; j++)
#pragma unroll
            for (int u = 0; u < 4; u++) acc[i][j][u] = 0.0f;

    float4 ax0 = *(const float4*)(xg);
    float4 ax1 = *(const float4*)(xg + 4);
    float4 bx0 = *(const float4*)(wg);
    float4 bx1 = *(const float4*)(wg + 4);

#define STORE_STAGE(s)                                                           \
    do {                                                                         \
        uint4 va = make_uint4(f2h2(ax0.x, ax0.y), f2h2(ax0.z, ax0.w),            \
                              f2h2(ax1.x, ax1.y), f2h2(ax1.z, ax1.w));           \
        uint4 vb = make_uint4(f2h2(bx0.x, bx0.y), f2h2(bx0.z, bx0.w),            \
                              f2h2(bx1.x, bx1.y), f2h2(bx1.z, bx1.w));           \
        *(uint4*)(Adst + (s) * STAGE_H) = va;                                    \
        *(uint4*)(Bdst + (s) * STAGE_H) = vb;                                    \
    } while (0)

    STORE_STAGE(0);
    __syncthreads();

    for (int kt = 0; kt < HKT; kt++) {
        const int cur = kt & 1;
        if (kt + 1 < HKT) {
            const float* xp = xg + (size_t)(kt + 1) * HBK;
            const float* wp = wg + (size_t)(kt + 1) * HBK;
            ax0 = *(const float4*)(xp);
            ax1 = *(const float4*)(xp + 4);
            bx0 = *(const float4*)(wp);
            bx1 = *(const float4*)(wp + 4);
        }

        const uint32_t a_s = a_base + cur * (STAGE_H * 2);
        const uint32_t b_s = b_base + cur * (STAGE_H * 2);
#pragma unroll
        for (int kk = 0; kk < 2; kk++) {
            uint32_t a0[4], a1[4], bf0[4], bf1[4];
            ldsm4(a0, a_s + a_off + (kk * 16) * 2);
            ldsm4(a1, a_s + a_off + (16 * HLD + kk * 16) * 2);
            ldsm4(bf0, b_s + b_off + (kk * 16) * 2);
            ldsm4(bf1, b_s + b_off + (16 * HLD + kk * 16) * 2);
            mma_h(acc[0][0], a0, bf0 + 0);
            mma_h(acc[0][1], a0, bf0 + 2);
            mma_h(acc[0][2], a0, bf1 + 0);
            mma_h(acc[0][3], a0, bf1 + 2);
            mma_h(acc[1][0], a1, bf0 + 0);
            mma_h(acc[1][1], a1, bf0 + 2);
            mma_h(acc[1][2], a1, bf1 + 0);
            mma_h(acc[1][3], a1, bf1 + 2);
        }

        if (kt + 1 < HKT) STORE_STAGE((kt + 1) & 1);
        __syncthreads();
    }
#undef STORE_STAGE

    // epilogue: add bias, store (c0,c1)->(row g), (c2,c3)->(row g+8)
#pragma unroll
    for (int nt = 0; nt < 4; nt++) {
        const int col = f0 + wn + nt * 8 + 2 * t;
        float2 bb = *(const float2*)(b + col);
#pragma unroll
        for (int mt = 0; mt < 2; mt++) {
            const int row = m0 + wm + mt * 16 + g;
            float2 v0 = make_float2(acc[mt][nt][0] + bb.x, acc[mt][nt][1] + bb.y);
            float2 v1 = make_float2(acc[mt][nt][2] + bb.x, acc[mt][nt][3] + bb.y);
            *(float2*)(pre + (size_t)row * D_SAE + col) = v0;
            *(float2*)(pre + (size_t)(row + 8) * D_SAE + col) = v1;
        }
    }
}

// ================= candidate collection: radix-select T64, keep val >= T64 - MARGIN =================
constexpr int TOPK_SMEM = D_SAE * 4;   // 64 KB row cache
#define SEL_MARGIN 2.5e-3f             // ~7 sigma of fp16-encoder noise

__global__ void __launch_bounds__(256)
topk_kernel(const float* __restrict__ pre) {
    extern __shared__ float sh[];
    __shared__ unsigned hist[256];
    __shared__ int s_digit, s_above, s_slot;

    const int n = blockIdx.x;
    const int tid = threadIdx.x;
    const float4* rowv = (const float4*)(pre + (size_t)n * D_SAE);
    float4* shv = (float4*)sh;

    for (int i = tid; i < D_SAE / 4; i += 256) shv[i] = rowv[i];
    __syncthreads();

    unsigned prefix = 0, mask = 0;
    int need = K_SP;
#pragma unroll
    for (int pass = 0; pass < 4; pass++) {
        int shift = 24 - 8 * pass;
        hist[tid] = 0;
        __syncthreads();
        for (int i = tid; i < D_SAE; i += 256) {
            unsigned k = fkey(sh[i]);
            if ((k & mask) == prefix) atomicAdd(&hist[(k >> shift) & 255u], 1u);
        }
        __syncthreads();
        if (tid == 0) {
            int cc = 0, d = 255;
            for (; d >= 0; d--) {
                int h = (int)hist[d];
                if (cc + h >= need) break;
                cc += h;
            }
            s_digit = d;
            s_above = cc;
        }
        __syncthreads();
        prefix |= ((unsigned)s_digit) << shift;
        mask   |= (0xFFu << shift);
        need   -= s_above;
        __syncthreads();
    }
    const float thresh = fkey_inv(prefix) - SEL_MARGIN;

    if (tid == 0) s_slot = 0;
    __syncthreads();

    for (int i = tid; i < D_SAE; i += 256) {
        if (sh[i] >= thresh) {
            int slot = atomicAdd(&s_slot, 1);
            if (slot < CAND_CAP) g_cand[n * CAND_CAP + slot] = i;
        }
    }
    __syncthreads();
    if (tid == 0) g_ccnt[n] = (s_slot < CAND_CAP) ? s_slot : CAND_CAP;
}

// ================= fp64 rescore + exact top-64 + write sparse row =================
__global__ void __launch_bounds__(256)
rescore_kernel(const float* __restrict__ x, const float* __restrict__ W,
               const float* __restrict__ pre, float* __restrict__ sparse) {
    __shared__ int    s_idx[CAND_CAP];
    __shared__ double s_val[CAND_CAP];

    const int n = blockIdx.x;
    const int tid = threadIdx.x;
    const int wid = tid >> 5;
    const int lane = tid & 31;

    const int c = g_ccnt[n];
    for (int i = tid; i < c; i += 256) s_idx[i] = g_cand[n * CAND_CAP + i];
    __syncthreads();

    const float* xr = x + (size_t)n * D_MODEL;

    for (int ci = wid; ci < c; ci += 8) {
        const float* wr = W + (size_t)s_idx[ci] * D_MODEL;
        double a0 = 0.0, a1 = 0.0, a2 = 0.0, a3 = 0.0;
        for (int kb = 0; kb < D_MODEL; kb += 128) {
            a0 = fma((double)xr[kb + lane],      (double)wr[kb + lane],      a0);
            a1 = fma((double)xr[kb + 32 + lane], (double)wr[kb + 32 + lane], a1);
            a2 = fma((double)xr[kb + 64 + lane], (double)wr[kb + 64 + lane], a2);
            a3 = fma((double)xr[kb + 96 + lane], (double)wr[kb + 96 + lane], a3);
        }
        double s = (a0 + a1) + (a2 + a3);
#pragma unroll
        for (int o = 16; o > 0; o >>= 1) s += __shfl_down_sync(0xFFFFFFFFu, s, o);
        if (lane == 0) s_val[ci] = s;
    }
    __syncthreads();

    float4* srow = (float4*)(sparse + (size_t)n * D_SAE);
    float4 z = make_float4(0.f, 0.f, 0.f, 0.f);
    for (int i = tid; i < D_SAE / 4; i += 256) srow[i] = z;
    __syncthreads();

    if (tid < c) {
        double v = s_val[tid];
        int my = s_idx[tid];
        int rank = 0;
        for (int j = 0; j < c; j++)
            rank += (s_val[j] > v) || (s_val[j] == v && s_idx[j] < my);
        if (rank < K_SP) {
            float pv = pre[(size_t)n * D_SAE + my];
            sparse[(size_t)n * D_SAE + my] = pv;
            g_tki[n * K_SP + rank] = my;
            g_tkv[n * K_SP + rank] = pv;
        }
    }
}

// ================= sparse decoder: recon = sum_j v_j * W_decT[f_j,:] + b_dec =================
__global__ void __launch_bounds__(256)
dec_kernel(const float* __restrict__ bdec, float* __restrict__ recon) {
    __shared__ float sv[K_SP];
    __shared__ int   si[K_SP];
    const int n = blockIdx.x;
    const int tid = threadIdx.x;
    if (tid < K_SP) { si[tid] = g_tki[n * K_SP + tid]; sv[tid] = g_tkv[n * K_SP + tid]; }
    __syncthreads();

    float4 accv[4];
    const float4* bv = (const float4*)bdec;
#pragma unroll
    for (int i = 0; i < 4; i++) accv[i] = bv[tid + 256 * i];

#pragma unroll 2
    for (int j = 0; j < K_SP; j++) {
        const float4* wr = (const float4*)(g_wdecT + (size_t)si[j] * D_MODEL);
        float v = sv[j];
#pragma unroll
        for (int i = 0; i < 4; i++) {
            float4 w = wr[tid + 256 * i];
            accv[i].x = fmaf(v, w.x, accv[i].x);
            accv[i].y = fmaf(v, w.y, accv[i].y);
            accv[i].z = fmaf(v, w.z, accv[i].z);
            accv[i].w = fmaf(v, w.w, accv[i].w);
        }
    }
    float4* out = (float4*)(recon + (size_t)n * D_MODEL);
#pragma unroll
    for (int i = 0; i < 4; i++) out[tid + 256 * i] = accv[i];
}

// ================= launch =================
extern "C" void kernel_launch(void* const* d_in, const int* in_sizes, int n_in,
                              void* d_out, int out_size) {
    const float* x     = (const float*)d_in[0];
    const float* W_enc = (const float*)d_in[1];
    const float* b_enc = (const float*)d_in[2];
    const float* W_dec = (const float*)d_in[3];
    const float* b_dec = (const float*)d_in[4];

    float* recon  = (float*)d_out;                              // (N, D)
    float* sparse = recon + (size_t)N_TOK * D_MODEL;            // (N, F)
    float* pre    = sparse + (size_t)N_TOK * D_SAE;             // (N, F)

    cudaFuncSetAttribute(topk_kernel, cudaFuncAttributeMaxDynamicSharedMemorySize, TOPK_SMEM);

    // shift the ncu -s window so the single captured launch lands on the encoder
    noop_kernel<<<1, 32>>>();
    noop_kernel<<<1, 32>>>();
    noop_kernel<<<1, 32>>>();

    transpose_kernel<<<dim3(D_SAE / 32, D_MODEL / 32), dim3(32, 8)>>>(W_dec);
    enc_h_kernel<<<(N_TOK / HBM) * (D_SAE / HBN), 512>>>(x, W_enc, b_enc, pre);
    topk_kernel<<<N_TOK, 256, TOPK_SMEM>>>(pre);
    rescore_kernel<<<N_TOK, 256>>>(x, W_enc, pre, sparse);
    dec_kernel<<<N_TOK, 256>>>(b_dec, recon);
}